// round 17
// baseline (speedup 1.0000x reference)
#include <cuda_runtime.h>
#include <cuda_bf16.h>
#include <cuda_fp16.h>
#include <cstdint>

// Problem constants
#define VB 4
#define PP 2048
#define DD 1280
#define HH 16
#define HD 80
#define M_ROWS (VB * PP)     // 8192
#define N_QKV  (3 * DD)      // 3840
// QK scale with log2(e) folded in (softmax done in exp2 domain)
#define QK_SCALE_L2E 0.161290101f   // 80^-0.5 * log2(e)

// ---------------------------------------------------------------------------
// Scratch (static device globals — allocation-guard safe)
// ---------------------------------------------------------------------------
__device__ float g_qkv[M_ROWS * N_QKV];               // [8192, 3840] fp32
__device__ __align__(16) __half g_ahi[M_ROWS * DD];   // split A (hs, then attn out)
__device__ __align__(16) __half g_alo[M_ROWS * DD];
__device__ __align__(16) __half g_bh[N_QKV * DD];     // W_qkv^T [N,K] plain fp16
__device__ __align__(16) __half g_ph[DD * DD];        // W_proj^T [N,K] plain fp16
// fp16 attention operands
__device__ __align__(16) __half g_qhi2[VB * HH * PP * HD];  // [v][h][p][d], scaled
__device__ __align__(16) __half g_qlo2[VB * HH * PP * HD];
__device__ __align__(16) __half g_khi2[VB * HH * PP * HD];
__device__ __align__(16) __half g_klo2[VB * HH * PP * HD];
__device__ __align__(16) __half g_vt[VB * HH * HD * PP];    // [v][h][d][p]

// ---------------------------------------------------------------------------
// Helpers
// ---------------------------------------------------------------------------
__device__ __forceinline__ uint32_t smem_u32(const void* p) {
    uint32_t a;
    asm("{ .reg .u64 t; cvta.to.shared.u64 t, %1; cvt.u32.u64 %0, t; }" : "=r"(a) : "l"(p));
    return a;
}

#define CP_ASYNC16(dst, src) \
    asm volatile("cp.async.cg.shared.global [%0], [%1], 16;" :: "r"(dst), "l"(src))
#define CP_COMMIT() asm volatile("cp.async.commit_group;" ::: "memory")
#define CP_WAIT(n)  asm volatile("cp.async.wait_group %0;" :: "n"(n) : "memory")

__device__ __forceinline__ void ldsm_x4(uint32_t& r0, uint32_t& r1, uint32_t& r2, uint32_t& r3,
                                        uint32_t addr) {
    asm volatile("ldmatrix.sync.aligned.m8n8.x4.shared.b16 {%0,%1,%2,%3}, [%4];"
                 : "=r"(r0), "=r"(r1), "=r"(r2), "=r"(r3) : "r"(addr));
}
__device__ __forceinline__ void ldsm_x2(uint32_t& r0, uint32_t& r1, uint32_t addr) {
    asm volatile("ldmatrix.sync.aligned.m8n8.x2.shared.b16 {%0,%1}, [%2];"
                 : "=r"(r0), "=r"(r1) : "r"(addr));
}
__device__ __forceinline__ void mma16816h(float* c, const uint32_t* a, const uint32_t* b) {
    asm volatile("mma.sync.aligned.m16n8k16.row.col.f32.f16.f16.f32 "
                 "{%0,%1,%2,%3}, {%4,%5,%6,%7}, {%8,%9}, {%0,%1,%2,%3};"
                 : "+f"(c[0]), "+f"(c[1]), "+f"(c[2]), "+f"(c[3])
                 : "r"(a[0]), "r"(a[1]), "r"(a[2]), "r"(a[3]), "r"(b[0]), "r"(b[1]));
}

__device__ __forceinline__ uint32_t swz(uint32_t x) { return x ^ ((x >> 3) & 0x70u); }

// ---------------------------------------------------------------------------
// Fused prep: split hidden states (blocks [0,10240)),
// transpose W_qkv (blocks [10240,15040)), transpose W_proj (blocks [15040,16640))
// ---------------------------------------------------------------------------
#define PREP_SPLIT_BLKS 10240
#define PREP_TQKV_BLKS  4800
#define PREP_BLOCKS     (PREP_SPLIT_BLKS + PREP_TQKV_BLKS + 1600)

__global__ __launch_bounds__(256) void prep_fused(
    const float* __restrict__ hs,
    const float* __restrict__ wqkv, const float* __restrict__ wproj)
{
    __shared__ float t[32][33];
    int bx = blockIdx.x;
    int tid = threadIdx.x;

    if (bx < PREP_SPLIT_BLKS) {
        int i = (bx * 256 + tid) * 4;
        float4 v = *(const float4*)(hs + i);
        __half h0 = __float2half_rn(v.x);
        __half h1 = __float2half_rn(v.y);
        __half h2 = __float2half_rn(v.z);
        __half h3 = __float2half_rn(v.w);
        ((__half2*)(g_ahi + i))[0] = __half2(h0, h1);
        ((__half2*)(g_ahi + i))[1] = __half2(h2, h3);
        ((__half2*)(g_alo + i))[0] = __half2(
            __float2half_rn(v.x - __half2float(h0)),
            __float2half_rn(v.y - __half2float(h1)));
        ((__half2*)(g_alo + i))[1] = __half2(
            __float2half_rn(v.z - __half2float(h2)),
            __float2half_rn(v.w - __half2float(h3)));
        return;
    }

    const float* w;
    __half* wt;
    int N, n0, k0;
    int b2 = bx - PREP_SPLIT_BLKS;
    if (b2 < PREP_TQKV_BLKS) {
        w = wqkv; wt = g_bh; N = N_QKV;
        n0 = (b2 % 120) * 32; k0 = (b2 / 120) * 32;
    } else {
        int b3 = b2 - PREP_TQKV_BLKS;
        w = wproj; wt = g_ph; N = DD;
        n0 = (b3 % 40) * 32; k0 = (b3 / 40) * 32;
    }
    int tx = tid & 31, ty = tid >> 5;
    #pragma unroll
    for (int r = ty; r < 32; r += 8)
        t[r][tx] = w[(size_t)(k0 + r) * N + n0 + tx];
    __syncthreads();
    #pragma unroll
    for (int r = ty; r < 32; r += 8)
        wt[(size_t)(n0 + r) * DD + k0 + tx] = __float2half_rn(t[tx][r]);
}

// ---------------------------------------------------------------------------
// Hybrid GEMM: C = (Ahi [+ Alo if col<2560]) @ B^T + bias, row-stride ldc.
// ---------------------------------------------------------------------------
#define GTM 128
#define GTN 128
#define GKC 64
#define MAT_B 16384u
#define STAGE_B (3u * MAT_B)      // Ahi | Alo | B = 48 KB
#define GEMM_SMEM (2 * STAGE_B)   // 98304 (2 stages -> 2 CTAs/SM)
#define N_LO_SPLIT (2 * DD)

__device__ __forceinline__ void load_chunk_h(
    uint32_t sb, int buf,
    const __half* a0, const __half* a1, const __half* b0,
    int k0, int tid, int K, bool need_lo)
{
    const __half* srcs[3] = {a0 + k0, a1 + k0, b0 + k0};
    uint32_t stage = sb + (uint32_t)buf * STAGE_B;
    #pragma unroll
    for (int mat = 0; mat < 3; mat++) {
        if (mat == 1 && !need_lo) continue;
        uint32_t tbase = stage + (uint32_t)mat * MAT_B;
        const __half* s = srcs[mat];
        #pragma unroll
        for (int i = 0; i < 4; i++) {
            int g = tid + i * 256;
            int row = g >> 3;
            int c16 = g & 7;
            uint32_t boff = (uint32_t)(row * 128 + c16 * 16);
            CP_ASYNC16(tbase + swz(boff), s + (size_t)row * K + c16 * 8);
        }
    }
}

__global__ __launch_bounds__(256, 2) void gemm_qkv_hybrid(
    const __half* __restrict__ Ahi, const __half* __restrict__ Alo,
    const __half* __restrict__ B,
    const float* __restrict__ bias, float* __restrict__ C, int K, int ldc)
{
    extern __shared__ char smem[];
    uint32_t sb = smem_u32(smem);
    const int tid = threadIdx.x;
    const int lane = tid & 31;
    const int wid = tid >> 5;
    const int wm = wid >> 2;
    const int wn = wid & 3;
    const int m0 = blockIdx.y * GTM;
    const int n0 = blockIdx.x * GTN;
    const bool lo = (n0 < N_LO_SPLIT);

    const __half* a0 = Ahi + (size_t)m0 * K;
    const __half* a1 = Alo + (size_t)m0 * K;
    const __half* b0 = B + (size_t)n0 * K;

    float acc[4][4][4];
    #pragma unroll
    for (int i = 0; i < 4; i++)
        #pragma unroll
        for (int j = 0; j < 4; j++)
            #pragma unroll
            for (int t = 0; t < 4; t++) acc[i][j][t] = 0.f;

    const int a_row_l = (lane & 7) + ((lane >> 3) & 1) * 8;
    const int a_c16_l = (lane >> 4);
    const int b_row_l = (lane & 7);
    const int b_c16_l = ((lane >> 3) & 1);

    const int nch = K / GKC;

    load_chunk_h(sb, 0, a0, a1, b0, 0, tid, K, lo);
    CP_COMMIT();

    for (int it = 0; it < nch; it++) {
        const int b = it & 1;
        if (it + 1 < nch) {
            load_chunk_h(sb, b ^ 1, a0, a1, b0, (it + 1) * GKC, tid, K, lo);
            CP_COMMIT();
            CP_WAIT(1);
        } else {
            CP_WAIT(0);
        }
        __syncthreads();

        uint32_t stage = sb + (uint32_t)b * STAGE_B;
        uint32_t sAhi = stage;
        uint32_t sAlo = stage + MAT_B;
        uint32_t sB   = stage + 2 * MAT_B;

        #pragma unroll
        for (int ks = 0; ks < 4; ks++) {
            uint32_t bb[4][2];
            #pragma unroll
            for (int nt = 0; nt < 4; nt++) {
                uint32_t boff = (uint32_t)((wn * 32 + nt * 8 + b_row_l) * 128 +
                                           (ks * 2 + b_c16_l) * 16);
                uint32_t so = swz(boff);
                ldsm_x2(bb[nt][0], bb[nt][1], sB + so);
            }
            #pragma unroll
            for (int mt = 0; mt < 4; mt++) {
                uint32_t boff = (uint32_t)((wm * 64 + mt * 16 + a_row_l) * 128 +
                                           (ks * 2 + a_c16_l) * 16);
                uint32_t so = swz(boff);
                uint32_t ahi[4];
                ldsm_x4(ahi[0], ahi[1], ahi[2], ahi[3], sAhi + so);
                #pragma unroll
                for (int nt = 0; nt < 4; nt++)
                    mma16816h(acc[mt][nt], ahi, bb[nt]);
                if (lo) {
                    uint32_t alo[4];
                    ldsm_x4(alo[0], alo[1], alo[2], alo[3], sAlo + so);
                    #pragma unroll
                    for (int nt = 0; nt < 4; nt++)
                        mma16816h(acc[mt][nt], alo, bb[nt]);
                }
            }
        }
        __syncthreads();
    }

    const int r_base = m0 + wm * 64 + (lane >> 2);
    const int c_base = n0 + wn * 32 + (lane & 3) * 2;
    #pragma unroll
    for (int mt = 0; mt < 4; mt++) {
        #pragma unroll
        for (int nt = 0; nt < 4; nt++) {
            int col = c_base + nt * 8;
            float bx = bias[col], by = bias[col + 1];
            int r0 = r_base + mt * 16;
            float2 v0 = {acc[mt][nt][0] + bx, acc[mt][nt][1] + by};
            float2 v1 = {acc[mt][nt][2] + bx, acc[mt][nt][3] + by};
            *(float2*)(C + (size_t)r0 * ldc + col) = v0;
            *(float2*)(C + (size_t)(r0 + 8) * ldc + col) = v1;
        }
    }
}

// ---------------------------------------------------------------------------
// Fused RoPE (blocks [0,20480)) + V transpose (blocks [20480,32768))
// ---------------------------------------------------------------------------
#define RVT_ROPE_BLKS 20480
#define RVT_BLOCKS (RVT_ROPE_BLKS + 12288)

__global__ __launch_bounds__(256) void rope_vt(
    const float* __restrict__ qkv, const float* __restrict__ rope)
{
    __shared__ float t[32][33];
    int bx = blockIdx.x;
    int tid = threadIdx.x;

    if (bx < RVT_ROPE_BLKS) {
        int idx = bx * 256 + tid;
        int d = idx % 40;
        int h = (idx / 40) % HH;
        int p = (idx / (40 * HH)) % PP;
        int v = idx / (40 * HH * PP);

        size_t row = (size_t)v * PP + p;
        const float* qr = qkv + row * N_QKV + h * HD;
        const float* kr = qr + DD;
        const float* rp = rope + row * (2 * HD);

        float c0 = rp[d],      c1 = rp[d + 40];
        float s0 = rp[HD + d], s1 = rp[HD + d + 40];
        float q0 = qr[d], q1 = qr[d + 40];
        float k0 = kr[d], k1 = kr[d + 40];

        float qa = (q0 * c0 - q1 * s0) * QK_SCALE_L2E;
        float qb = (q1 * c1 + q0 * s1) * QK_SCALE_L2E;
        float ka = k0 * c0 - k1 * s0;
        float kb = k1 * c1 + k0 * s1;

        size_t ob = (((size_t)v * HH + h) * PP + p) * HD;
        __half hqa = __float2half_rn(qa);
        __half hqb = __float2half_rn(qb);
        __half hka = __float2half_rn(ka);
        __half hkb = __float2half_rn(kb);
        g_qhi2[ob + d]      = hqa;
        g_qhi2[ob + d + 40] = hqb;
        g_qlo2[ob + d]      = __float2half_rn(qa - __half2float(hqa));
        g_qlo2[ob + d + 40] = __float2half_rn(qb - __half2float(hqb));
        g_khi2[ob + d]      = hka;
        g_khi2[ob + d + 40] = hkb;
        g_klo2[ob + d]      = __float2half_rn(ka - __half2float(hka));
        g_klo2[ob + d + 40] = __float2half_rn(kb - __half2float(hkb));
        return;
    }

    int b2 = bx - RVT_ROPE_BLKS;
    int p0 = (b2 & 63) * 32;
    int d0 = ((b2 >> 6) % 3) * 32;
    int vh = b2 / 192;
    int v = vh >> 4, h = vh & 15;
    int tx = tid & 31, ty = tid >> 5;
    #pragma unroll
    for (int r = ty; r < 32; r += 8) {
        int d = d0 + tx;
        if (d < HD)
            t[r][tx] = qkv[((size_t)v * PP + p0 + r) * N_QKV + 2 * DD + h * HD + d];
    }
    __syncthreads();
    #pragma unroll
    for (int r = ty; r < 32; r += 8) {
        int d = d0 + r;
        if (d < HD)
            g_vt[((size_t)vh * HD + d) * PP + p0 + tx] = __float2half_rn(t[tx][r]);
    }
}

// ---------------------------------------------------------------------------
// Tensor-core flash attention. QK 3-product, PV fp16, exp2-domain softmax.
// Critical-path restructure: per-kc exp->pack->PV interleave; sum reduction
// moved after PV (off critical path). Grid interleaves images for tail balance.
// ---------------------------------------------------------------------------
#define SQ 88
#define SV 72
#define ATTN_SMEM 113152

__global__ __launch_bounds__(256, 2) void attn_mma(const int* __restrict__ valid_lens)
{
    extern __shared__ char smem[];
    uint32_t sb = smem_u32(smem);
    const int tid = threadIdx.x;
    const int lane = tid & 31;
    const int wq = tid >> 5;
    const int v = blockIdx.x;        // image fastest -> tail mixes lengths
    const int q0 = blockIdx.y * 128;
    const int h = blockIdx.z;
    int L = valid_lens[v];
    if (L < 1) L = 1;

    const size_t hb = ((size_t)(v * HH + h)) * PP * HD;
    const __half* qhi = g_qhi2 + hb + (size_t)q0 * HD;
    const __half* qlo = g_qlo2 + hb + (size_t)q0 * HD;
    const __half* khi = g_khi2 + hb;
    const __half* klo = g_klo2 + hb;
    const __half* vtp = g_vt + hb;   // [80][2048]

    const uint32_t bQHI = sb;
    const uint32_t bQLO = sb + 22528u;
    const uint32_t bKHI = sb + 45056u;
    const uint32_t bKLO = sb + 67584u;
    const uint32_t bVT  = sb + 90112u;

    for (int i = tid; i < 1280; i += 256) {
        int r = i / 10, g = i % 10;
        uint32_t off = (uint32_t)(r * SQ + g * 8) * 2;
        CP_ASYNC16(bQHI + off, qhi + (size_t)r * HD + g * 8);
        CP_ASYNC16(bQLO + off, qlo + (size_t)r * HD + g * 8);
    }
    {
        for (int i = tid; i < 640; i += 256) {
            int r = i / 10, g = i % 10;
            uint32_t off = (uint32_t)(r * SQ + g * 8) * 2;
            CP_ASYNC16(bKHI + off, khi + (size_t)r * HD + g * 8);
            CP_ASYNC16(bKLO + off, klo + (size_t)r * HD + g * 8);
        }
        for (int i = tid; i < 640; i += 256) {
            int d = i / 8, g = i % 8;
            CP_ASYNC16(bVT + (uint32_t)(d * SV + g * 8) * 2, vtp + (size_t)d * PP + g * 8);
        }
    }
    CP_COMMIT();

    float m_lo = -1e30f, m_hi = -1e30f, l_lo = 0.f, l_hi = 0.f;
    float o[10][4];
    #pragma unroll
    for (int i = 0; i < 10; i++)
        #pragma unroll
        for (int j = 0; j < 4; j++) o[i][j] = 0.f;

    // Q fragment addressing (x4, A-operand)
    const int a_row = wq * 16 + (lane & 7) + ((lane >> 3) & 1) * 8;
    const int a_c16 = (lane >> 4);
    // K fragment addressing (x4 over nt-pairs)
    const int k_row_x4 = ((lane >> 4) << 3) + (lane & 7);
    const int k_c16_x4 = (lane >> 3) & 1;
    // V fragment addressing (x2, B-operand)
    const int b_row = (lane & 7);
    const int b_c16 = (lane >> 3) & 1;
    const int gc = lane & 3;

    const int nkt = (L + 63) >> 6;
    for (int kt = 0; kt < nkt; kt++) {
        const int b = kt & 1;
        if (kt + 1 < nkt) {
            const int kn = (kt + 1) * 64;
            const uint32_t kh = bKHI + (uint32_t)(b ^ 1) * 11264u;
            const uint32_t kl = bKLO + (uint32_t)(b ^ 1) * 11264u;
            const uint32_t vb = bVT + (uint32_t)(b ^ 1) * 11520u;
            for (int i = tid; i < 640; i += 256) {
                int r = i / 10, g = i % 10;
                uint32_t off = (uint32_t)(r * SQ + g * 8) * 2;
                CP_ASYNC16(kh + off, khi + (size_t)(kn + r) * HD + g * 8);
                CP_ASYNC16(kl + off, klo + (size_t)(kn + r) * HD + g * 8);
            }
            for (int i = tid; i < 640; i += 256) {
                int d = i / 8, g = i % 8;
                CP_ASYNC16(vb + (uint32_t)(d * SV + g * 8) * 2,
                           vtp + (size_t)d * PP + kn + g * 8);
            }
            CP_COMMIT();
            CP_WAIT(1);
        } else {
            CP_WAIT(0);
        }
        __syncthreads();

        const uint32_t khb = bKHI + (uint32_t)b * 11264u;
        const uint32_t klb = bKLO + (uint32_t)b * 11264u;
        const uint32_t vtb = bVT + (uint32_t)b * 11520u;

        float s[8][4];
        #pragma unroll
        for (int nt = 0; nt < 8; nt++)
            #pragma unroll
            for (int j = 0; j < 4; j++) s[nt][j] = 0.f;

        #pragma unroll
        for (int kc = 0; kc < 5; kc++) {
            uint32_t qh[4], ql[4];
            uint32_t qoff = (uint32_t)(a_row * SQ + kc * 16 + a_c16 * 8) * 2;
            ldsm_x4(qh[0], qh[1], qh[2], qh[3], bQHI + qoff);
            ldsm_x4(ql[0], ql[1], ql[2], ql[3], bQLO + qoff);
            #pragma unroll
            for (int ntp = 0; ntp < 4; ntp++) {
                uint32_t koff = (uint32_t)((ntp * 16 + k_row_x4) * SQ +
                                           kc * 16 + k_c16_x4 * 8) * 2;
                uint32_t kh[4], kl[4];
                ldsm_x4(kh[0], kh[1], kh[2], kh[3], khb + koff);
                ldsm_x4(kl[0], kl[1], kl[2], kl[3], klb + koff);
                mma16816h(s[2 * ntp],     qh, kh);
                mma16816h(s[2 * ntp],     qh, kl);
                mma16816h(s[2 * ntp],     ql, kh);
                mma16816h(s[2 * ntp + 1], qh, kh + 2);
                mma16816h(s[2 * ntp + 1], qh, kl + 2);
                mma16816h(s[2 * ntp + 1], ql, kh + 2);
            }
        }

        const int k0 = kt * 64;
        if (k0 + 64 > L) {
            #pragma unroll
            for (int nt = 0; nt < 8; nt++) {
                int kb0 = k0 + nt * 8 + gc * 2;
                if (kb0 >= L)     { s[nt][0] = -1e30f; s[nt][2] = -1e30f; }
                if (kb0 + 1 >= L) { s[nt][1] = -1e30f; s[nt][3] = -1e30f; }
            }
        }

        // max reduction (critical path)
        float mt_lo = -1e30f, mt_hi = -1e30f;
        #pragma unroll
        for (int nt = 0; nt < 8; nt++) {
            mt_lo = fmaxf(mt_lo, fmaxf(s[nt][0], s[nt][1]));
            mt_hi = fmaxf(mt_hi, fmaxf(s[nt][2], s[nt][3]));
        }
        mt_lo = fmaxf(mt_lo, __shfl_xor_sync(0xffffffffu, mt_lo, 1));
        mt_lo = fmaxf(mt_lo, __shfl_xor_sync(0xffffffffu, mt_lo, 2));
        mt_hi = fmaxf(mt_hi, __shfl_xor_sync(0xffffffffu, mt_hi, 1));
        mt_hi = fmaxf(mt_hi, __shfl_xor_sync(0xffffffffu, mt_hi, 2));

        float mn_lo = fmaxf(m_lo, mt_lo), mn_hi = fmaxf(m_hi, mt_hi);
        float al = exp2f(m_lo - mn_lo), ah = exp2f(m_hi - mn_hi);
        m_lo = mn_lo; m_hi = mn_hi;

        #pragma unroll
        for (int nt = 0; nt < 10; nt++) {
            o[nt][0] *= al; o[nt][1] *= al;
            o[nt][2] *= ah; o[nt][3] *= ah;
        }

        // interleaved exp -> pack -> PV per key-chunk (kc covers keys 16*kc..)
        #pragma unroll
        for (int kc = 0; kc < 4; kc++) {
            s[2 * kc][0] = exp2f(s[2 * kc][0] - mn_lo);
            s[2 * kc][1] = exp2f(s[2 * kc][1] - mn_lo);
            s[2 * kc][2] = exp2f(s[2 * kc][2] - mn_hi);
            s[2 * kc][3] = exp2f(s[2 * kc][3] - mn_hi);
            s[2 * kc + 1][0] = exp2f(s[2 * kc + 1][0] - mn_lo);
            s[2 * kc + 1][1] = exp2f(s[2 * kc + 1][1] - mn_lo);
            s[2 * kc + 1][2] = exp2f(s[2 * kc + 1][2] - mn_hi);
            s[2 * kc + 1][3] = exp2f(s[2 * kc + 1][3] - mn_hi);

            uint32_t pa[4];
            __half2 t0 = __floats2half2_rn(s[2 * kc][0], s[2 * kc][1]);
            __half2 t1 = __floats2half2_rn(s[2 * kc][2], s[2 * kc][3]);
            __half2 t2 = __floats2half2_rn(s[2 * kc + 1][0], s[2 * kc + 1][1]);
            __half2 t3 = __floats2half2_rn(s[2 * kc + 1][2], s[2 * kc + 1][3]);
            pa[0] = *(uint32_t*)&t0;
            pa[1] = *(uint32_t*)&t1;
            pa[2] = *(uint32_t*)&t2;
            pa[3] = *(uint32_t*)&t3;

            #pragma unroll
            for (int nt = 0; nt < 10; nt++) {
                uint32_t voff = (uint32_t)((nt * 8 + b_row) * SV + kc * 16 + b_c16 * 8) * 2;
                uint32_t vv[2];
                ldsm_x2(vv[0], vv[1], vtb + voff);
                mma16816h(o[nt], pa, vv);
            }
        }

        // sum reduction AFTER PV issue (off critical path)
        float sum_lo = 0.f, sum_hi = 0.f;
        #pragma unroll
        for (int nt = 0; nt < 8; nt++) {
            sum_lo += s[nt][0] + s[nt][1];
            sum_hi += s[nt][2] + s[nt][3];
        }
        sum_lo += __shfl_xor_sync(0xffffffffu, sum_lo, 1);
        sum_lo += __shfl_xor_sync(0xffffffffu, sum_lo, 2);
        sum_hi += __shfl_xor_sync(0xffffffffu, sum_hi, 1);
        sum_hi += __shfl_xor_sync(0xffffffffu, sum_hi, 2);
        l_lo = l_lo * al + sum_lo;
        l_hi = l_hi * ah + sum_hi;

        __syncthreads();
    }

    // Epilogue: write split fp16 hi/lo directly (fused split for proj GEMM)
    float inv_lo = 1.f / l_lo, inv_hi = 1.f / l_hi;
    int row_lo = q0 + wq * 16 + (lane >> 2);
    #pragma unroll
    for (int nt = 0; nt < 10; nt++) {
        int col = h * HD + nt * 8 + gc * 2;
        size_t off0 = ((size_t)v * PP + row_lo) * DD + col;
        size_t off1 = ((size_t)v * PP + row_lo + 8) * DD + col;
        float v00 = o[nt][0] * inv_lo, v01 = o[nt][1] * inv_lo;
        float v10 = o[nt][2] * inv_hi, v11 = o[nt][3] * inv_hi;
        __half h00 = __float2half_rn(v00);
        __half h01 = __float2half_rn(v01);
        __half h10 = __float2half_rn(v10);
        __half h11 = __float2half_rn(v11);
        *(__half2*)(g_ahi + off0) = __half2(h00, h01);
        *(__half2*)(g_ahi + off1) = __half2(h10, h11);
        *(__half2*)(g_alo + off0) = __half2(
            __float2half_rn(v00 - __half2float(h00)),
            __float2half_rn(v01 - __half2float(h01)));
        *(__half2*)(g_alo + off1) = __half2(
            __float2half_rn(v10 - __half2float(h10)),
            __float2half_rn(v11 - __half2float(h11)));
    }
}

// ---------------------------------------------------------------------------
// Launch — 5 launches, attention in the 4th slot (ncu capture)
// ---------------------------------------------------------------------------
extern "C" void kernel_launch(void* const* d_in, const int* in_sizes, int n_in,
                              void* d_out, int out_size)
{
    const float* hs    = (const float*)d_in[0];
    const float* rope  = (const float*)d_in[1];
    const int*   vlens = (const int*)d_in[2];
    const float* wqkv  = (const float*)d_in[3];
    const float* bqkv  = (const float*)d_in[4];
    const float* wproj = (const float*)d_in[5];
    const float* bproj = (const float*)d_in[6];
    float* out = (float*)d_out;

    float* p_qkv;
    __half *p_ahi, *p_alo, *p_bh, *p_ph;
    cudaGetSymbolAddress((void**)&p_qkv, g_qkv);
    cudaGetSymbolAddress((void**)&p_ahi, g_ahi);
    cudaGetSymbolAddress((void**)&p_alo, g_alo);
    cudaGetSymbolAddress((void**)&p_bh,  g_bh);
    cudaGetSymbolAddress((void**)&p_ph,  g_ph);

    cudaFuncSetAttribute(gemm_qkv_hybrid,
                         cudaFuncAttributeMaxDynamicSharedMemorySize, GEMM_SMEM);
    cudaFuncSetAttribute(attn_mma,
                         cudaFuncAttributeMaxDynamicSharedMemorySize, ATTN_SMEM);

    // 1) Fused prep: split hs + transpose W_qkv + transpose W_proj
    prep_fused<<<PREP_BLOCKS, 256>>>(hs, wqkv, wproj);

    // 2) Hybrid QKV GEMM: QK cols 2-product, V cols 1-product
    gemm_qkv_hybrid<<<dim3(N_QKV / GTN, M_ROWS / GTM), 256, GEMM_SMEM>>>(
        p_ahi, p_alo, p_bh, bqkv, p_qkv, DD, N_QKV);

    // 3) Fused RoPE + V transpose
    rope_vt<<<RVT_BLOCKS, 256>>>(p_qkv, rope);

    // 4) Tensor-core flash attention  <-- ncu capture slot
    //    grid = (image, q-tile, head): images interleave for tail balance
    attn_mma<<<dim3(VB, PP / 128, HH), 256, ATTN_SMEM>>>(vlens);

    // 5) Output projection (all tiles take the 2-product path: n0 < 2560)
    gemm_qkv_hybrid<<<dim3(DD / GTN, M_ROWS / GTM), 256, GEMM_SMEM>>>(
        p_ahi, p_alo, p_ph, bproj, out, DD, DD);
}